// round 1
// baseline (speedup 1.0000x reference)
#include <cuda_runtime.h>
#include <math.h>

#define NN    50000
#define EE    400000
#define HID   128
#define NRBF  32
#define EDGEF 16
#define MLP_IN 432   // 128 + 128 + 32 + 128 + 16

// RBF: offsets = linspace(0, 5, 32); delta = 5/31; coeff = -0.5/delta^2 = -961/50
#define RBF_COEFF (-19.22f)

// -------- scratch (static device globals; no allocation allowed) --------
__device__ float g_v1[(size_t)NN * 3 * HID];     // vecp[:, :,   0:128]
__device__ float g_v2[(size_t)NN * 3 * HID];     // vecp[:, :, 128:256]
__device__ float g_v3[(size_t)NN * 3 * HID];     // vecp[:, :, 256:384]
__device__ float g_vdot[(size_t)NN * HID];       // sum_v vec1*vec2
__device__ float g_haggr[(size_t)NN * HID];      // segment_sum(msg_h)
__device__ float g_vaggr[(size_t)NN * 3 * HID];  // segment_sum(vec_msg)

// ======================= zero the accumulators =======================
__global__ void k_zero() {
    int i = blockIdx.x * blockDim.x + threadIdx.x;
    const int n1 = NN * HID / 4;          // 1.6M float4
    float4 z = make_float4(0.f, 0.f, 0.f, 0.f);
    if (i < n1) reinterpret_cast<float4*>(g_haggr)[i] = z;
    else        reinterpret_cast<float4*>(g_vaggr)[i - n1] = z;   // 4.8M float4
}

// ======================= node pre: vecp = vec @ Wvp =======================
// 8 nodes / CTA of 128 threads. Thread (u = tid&31, g = tid>>5) owns
// nodes {2g, 2g+1} x 3 dirs x 12 output channels {4u..4u+3} x {o=0,1,2}.
__global__ __launch_bounds__(128) void k_node_pre(const float* __restrict__ vec,
                                                  const float* __restrict__ Wvp) {
    __shared__ __align__(16) float vsh[8][3][HID];   // 12 KB
    const int n0 = blockIdx.x * 8;
    const int tid = threadIdx.x;
    for (int idx = tid; idx < 8 * 3 * HID; idx += 128)
        ((float*)vsh)[idx] = vec[(size_t)n0 * 3 * HID + idx];
    __syncthreads();

    const int u = tid & 31, g = tid >> 5;
    float a[2][3][3][4];
    #pragma unroll
    for (int r = 0; r < 2; r++)
        #pragma unroll
        for (int v = 0; v < 3; v++)
            #pragma unroll
            for (int o = 0; o < 3; o++)
                #pragma unroll
                for (int q = 0; q < 4; q++) a[r][v][o][q] = 0.f;

    for (int i = 0; i < HID; i++) {
        float4 w0 = *(const float4*)&Wvp[i * 384 + 4 * u];
        float4 w1 = *(const float4*)&Wvp[i * 384 + 128 + 4 * u];
        float4 w2 = *(const float4*)&Wvp[i * 384 + 256 + 4 * u];
        float wa[4] = {w0.x, w0.y, w0.z, w0.w};
        float wb[4] = {w1.x, w1.y, w1.z, w1.w};
        float wc[4] = {w2.x, w2.y, w2.z, w2.w};
        #pragma unroll
        for (int r = 0; r < 2; r++) {
            #pragma unroll
            for (int v = 0; v < 3; v++) {
                float x = vsh[2 * g + r][v][i];
                #pragma unroll
                for (int q = 0; q < 4; q++) {
                    a[r][v][0][q] += x * wa[q];
                    a[r][v][1][q] += x * wb[q];
                    a[r][v][2][q] += x * wc[q];
                }
            }
        }
    }

    #pragma unroll
    for (int r = 0; r < 2; r++) {
        int n = n0 + 2 * g + r;
        float vd[4] = {0.f, 0.f, 0.f, 0.f};
        #pragma unroll
        for (int v = 0; v < 3; v++) {
            size_t base = ((size_t)n * 3 + v) * HID + 4 * u;
            *(float4*)&g_v1[base] = make_float4(a[r][v][0][0], a[r][v][0][1], a[r][v][0][2], a[r][v][0][3]);
            *(float4*)&g_v2[base] = make_float4(a[r][v][1][0], a[r][v][1][1], a[r][v][1][2], a[r][v][1][3]);
            *(float4*)&g_v3[base] = make_float4(a[r][v][2][0], a[r][v][2][1], a[r][v][2][2], a[r][v][2][3]);
            #pragma unroll
            for (int q = 0; q < 4; q++) vd[q] += a[r][v][0][q] * a[r][v][1][q];
        }
        *(float4*)&g_vdot[(size_t)n * HID + 4 * u] = make_float4(vd[0], vd[1], vd[2], vd[3]);
    }
}

// ======================= edge kernel: gather + MLP + scatter =======================
// 16 edges / CTA of 128 threads. MLP phases: thread (u, g) owns a 4-edge x 4-channel
// register tile -> each shared broadcast load feeds 4 FMAs, each LDG.128 feeds 16.
__global__ __launch_bounds__(128) void k_edge(const float* __restrict__ h,
                                              const float* __restrict__ coord,
                                              const int*   __restrict__ ei,
                                              const float* __restrict__ eattr,
                                              const float* __restrict__ W1, const float* __restrict__ b1,
                                              const float* __restrict__ W2, const float* __restrict__ b2,
                                              const float* __restrict__ W3, const float* __restrict__ b3) {
    __shared__ __align__(16) float in_sh[16][MLP_IN];  // 27.6 KB
    __shared__ __align__(16) float x_sh[16][HID];      // 8 KB
    __shared__ __align__(16) float y_sh[16][HID];      // 8 KB
    __shared__ int   row_sh[16], col_sh[16];
    __shared__ float xij_sh[16][3];
    __shared__ float d_sh[16];

    const int e0  = blockIdx.x * 16;
    const int tid = threadIdx.x;

    if (tid < 16) {
        int e = e0 + tid;
        int r = ei[e], c = ei[EE + e];
        row_sh[tid] = r; col_sh[tid] = c;
        float dx = coord[3 * r + 0] - coord[3 * c + 0];
        float dy = coord[3 * r + 1] - coord[3 * c + 1];
        float dz = coord[3 * r + 2] - coord[3 * c + 2];
        xij_sh[tid][0] = dx; xij_sh[tid][1] = dy; xij_sh[tid][2] = dz;
        d_sh[tid] = sqrtf(dx * dx + dy * dy + dz * dz + 1e-8f);
    }
    __syncthreads();

    // gather: h[row], h[col], cross = sum_v vec1[row]*vec2[col]
    #pragma unroll 1
    for (int e = 0; e < 16; e++) {
        int r = row_sh[e], c = col_sh[e];
        in_sh[e][tid]       = h[(size_t)r * HID + tid];
        in_sh[e][HID + tid] = h[(size_t)c * HID + tid];
        float cr = 0.f;
        #pragma unroll
        for (int v = 0; v < 3; v++)
            cr += g_v1[((size_t)r * 3 + v) * HID + tid] * g_v2[((size_t)c * 3 + v) * HID + tid];
        in_sh[e][288 + tid] = cr;     // cross at offset 2*HID + NRBF = 288
    }
    // rbf (offset 256) + edge_attr (offset 416)
    for (int idx = tid; idx < 16 * (NRBF + EDGEF); idx += 128) {
        int e = idx / (NRBF + EDGEF);
        int t = idx % (NRBF + EDGEF);
        if (t < NRBF) {
            float off = 5.0f * (float)t / 31.0f;
            float dd  = d_sh[e] - off;
            in_sh[e][256 + t] = expf(RBF_COEFF * dd * dd);
        } else {
            in_sh[e][416 + (t - NRBF)] = eattr[(size_t)(e0 + e) * EDGEF + (t - NRBF)];
        }
    }
    __syncthreads();

    const int u = tid & 31, g = tid >> 5;   // channels 4u..4u+3, edges 4g..4g+3

    // ---- layer 1: [432] -> [128], silu ----
    {
        float acc[4][4];
        #pragma unroll
        for (int r = 0; r < 4; r++)
            #pragma unroll
            for (int q = 0; q < 4; q++) acc[r][q] = 0.f;
        for (int i = 0; i < MLP_IN; i++) {
            float4 w4 = *(const float4*)&W1[(size_t)i * HID + 4 * u];
            float w[4] = {w4.x, w4.y, w4.z, w4.w};
            #pragma unroll
            for (int r = 0; r < 4; r++) {
                float av = in_sh[4 * g + r][i];
                #pragma unroll
                for (int q = 0; q < 4; q++) acc[r][q] += av * w[q];
            }
        }
        float4 b4 = *(const float4*)&b1[4 * u];
        float bb[4] = {b4.x, b4.y, b4.z, b4.w};
        #pragma unroll
        for (int r = 0; r < 4; r++) {
            float s[4];
            #pragma unroll
            for (int q = 0; q < 4; q++) {
                float z = acc[r][q] + bb[q];
                s[q] = z / (1.f + expf(-z));
            }
            *(float4*)&x_sh[4 * g + r][4 * u] = make_float4(s[0], s[1], s[2], s[3]);
        }
    }
    __syncthreads();

    // ---- layer 2: [128] -> [128], silu ----
    {
        float acc[4][4];
        #pragma unroll
        for (int r = 0; r < 4; r++)
            #pragma unroll
            for (int q = 0; q < 4; q++) acc[r][q] = 0.f;
        for (int i = 0; i < HID; i++) {
            float4 w4 = *(const float4*)&W2[(size_t)i * HID + 4 * u];
            float w[4] = {w4.x, w4.y, w4.z, w4.w};
            #pragma unroll
            for (int r = 0; r < 4; r++) {
                float av = x_sh[4 * g + r][i];
                #pragma unroll
                for (int q = 0; q < 4; q++) acc[r][q] += av * w[q];
            }
        }
        float4 b4 = *(const float4*)&b2[4 * u];
        float bb[4] = {b4.x, b4.y, b4.z, b4.w};
        #pragma unroll
        for (int r = 0; r < 4; r++) {
            float s[4];
            #pragma unroll
            for (int q = 0; q < 4; q++) {
                float z = acc[r][q] + bb[q];
                s[q] = z / (1.f + expf(-z));
            }
            *(float4*)&y_sh[4 * g + r][4 * u] = make_float4(s[0], s[1], s[2], s[3]);
        }
    }
    __syncthreads();

    // ---- layer 3: [128] -> [384] = (msg_h | msg_v | msg_x), then scatter ----
    {
        float ah[4][4], av_[4][4], ax[4][4];
        #pragma unroll
        for (int r = 0; r < 4; r++)
            #pragma unroll
            for (int q = 0; q < 4; q++) { ah[r][q] = 0.f; av_[r][q] = 0.f; ax[r][q] = 0.f; }
        for (int i = 0; i < HID; i++) {
            float4 h4 = *(const float4*)&W3[(size_t)i * 384 + 4 * u];
            float4 v4 = *(const float4*)&W3[(size_t)i * 384 + 128 + 4 * u];
            float4 x4 = *(const float4*)&W3[(size_t)i * 384 + 256 + 4 * u];
            float wh[4] = {h4.x, h4.y, h4.z, h4.w};
            float wv[4] = {v4.x, v4.y, v4.z, v4.w};
            float wx[4] = {x4.x, x4.y, x4.z, x4.w};
            #pragma unroll
            for (int r = 0; r < 4; r++) {
                float a = y_sh[4 * g + r][i];
                #pragma unroll
                for (int q = 0; q < 4; q++) {
                    ah[r][q]  += a * wh[q];
                    av_[r][q] += a * wv[q];
                    ax[r][q]  += a * wx[q];
                }
            }
        }
        float4 bh4 = *(const float4*)&b3[4 * u];
        float4 bv4 = *(const float4*)&b3[128 + 4 * u];
        float4 bx4 = *(const float4*)&b3[256 + 4 * u];
        float bh[4] = {bh4.x, bh4.y, bh4.z, bh4.w};
        float bv[4] = {bv4.x, bv4.y, bv4.z, bv4.w};
        float bx[4] = {bx4.x, bx4.y, bx4.z, bx4.w};

        #pragma unroll 1
        for (int r = 0; r < 4; r++) {
            int e  = 4 * g + r;
            int ro = row_sh[e], co = col_sh[e];
            float xx = xij_sh[e][0], xy = xij_sh[e][1], xz = xij_sh[e][2];
            float4 v30 = *(const float4*)&g_v3[((size_t)co * 3 + 0) * HID + 4 * u];
            float4 v31 = *(const float4*)&g_v3[((size_t)co * 3 + 1) * HID + 4 * u];
            float4 v32 = *(const float4*)&g_v3[((size_t)co * 3 + 2) * HID + 4 * u];
            float w0[4] = {v30.x, v30.y, v30.z, v30.w};
            float w1[4] = {v31.x, v31.y, v31.z, v31.w};
            float w2[4] = {v32.x, v32.y, v32.z, v32.w};
            #pragma unroll
            for (int q = 0; q < 4; q++) {
                int ch = 4 * u + q;
                float mh = ah[r][q]  + bh[q];
                float mv = av_[r][q] + bv[q];
                float mx = ax[r][q]  + bx[q];
                atomicAdd(&g_haggr[(size_t)ro * HID + ch], mh);
                atomicAdd(&g_vaggr[((size_t)ro * 3 + 0) * HID + ch], w0[q] * mv + mx * xx);
                atomicAdd(&g_vaggr[((size_t)ro * 3 + 1) * HID + ch], w1[q] * mv + mx * xy);
                atomicAdd(&g_vaggr[((size_t)ro * 3 + 2) * HID + ch], w2[q] * mv + mx * xz);
            }
        }
    }
}

// ======================= node out: o = h_aggr @ Wop + bop; epilogue =======================
// 16 nodes / CTA of 128 threads; thread owns 4 nodes x 4 channels x {o1,o2,o3}.
__global__ __launch_bounds__(128) void k_node_out(const float* __restrict__ Wop,
                                                  const float* __restrict__ bop,
                                                  float* __restrict__ out) {
    __shared__ __align__(16) float hsh[16][HID];   // 8 KB
    const int n0 = blockIdx.x * 16;
    const int tid = threadIdx.x;
    for (int idx = tid; idx < 16 * HID; idx += 128)
        ((float*)hsh)[idx] = g_haggr[(size_t)n0 * HID + idx];
    __syncthreads();

    const int u = tid & 31, g = tid >> 5;
    float o1[4][4], o2[4][4], o3[4][4];
    #pragma unroll
    for (int r = 0; r < 4; r++)
        #pragma unroll
        for (int q = 0; q < 4; q++) { o1[r][q] = 0.f; o2[r][q] = 0.f; o3[r][q] = 0.f; }

    for (int i = 0; i < HID; i++) {
        float4 a4 = *(const float4*)&Wop[(size_t)i * 384 + 4 * u];
        float4 b4 = *(const float4*)&Wop[(size_t)i * 384 + 128 + 4 * u];
        float4 c4 = *(const float4*)&Wop[(size_t)i * 384 + 256 + 4 * u];
        float wa[4] = {a4.x, a4.y, a4.z, a4.w};
        float wb[4] = {b4.x, b4.y, b4.z, b4.w};
        float wc[4] = {c4.x, c4.y, c4.z, c4.w};
        #pragma unroll
        for (int r = 0; r < 4; r++) {
            float x = hsh[4 * g + r][i];
            #pragma unroll
            for (int q = 0; q < 4; q++) {
                o1[r][q] += x * wa[q];
                o2[r][q] += x * wb[q];
                o3[r][q] += x * wc[q];
            }
        }
    }

    float4 ba4 = *(const float4*)&bop[4 * u];
    float4 bb4 = *(const float4*)&bop[128 + 4 * u];
    float4 bc4 = *(const float4*)&bop[256 + 4 * u];
    float ba[4] = {ba4.x, ba4.y, ba4.z, ba4.w};
    float bb[4] = {bb4.x, bb4.y, bb4.z, bb4.w};
    float bc[4] = {bc4.x, bc4.y, bc4.z, bc4.w};

    #pragma unroll 1
    for (int r = 0; r < 4; r++) {
        int n = n0 + 4 * g + r;
        float4 vd4 = *(const float4*)&g_vdot[(size_t)n * HID + 4 * u];
        float vd[4] = {vd4.x, vd4.y, vd4.z, vd4.w};
        float dh[4], O1[4];
        #pragma unroll
        for (int q = 0; q < 4; q++) {
            O1[q]    = o1[r][q] + ba[q];
            float O2 = o2[r][q] + bb[q];
            float O3 = o3[r][q] + bc[q];
            dh[q] = vd[q] * O2 + O3;
        }
        *(float4*)&out[(size_t)n * HID + 4 * u] = make_float4(dh[0], dh[1], dh[2], dh[3]);
        #pragma unroll
        for (int v = 0; v < 3; v++) {
            size_t base = ((size_t)n * 3 + v) * HID + 4 * u;
            float4 v34 = *(const float4*)&g_v3[base];
            float4 va4 = *(const float4*)&g_vaggr[base];
            float v3[4] = {v34.x, v34.y, v34.z, v34.w};
            float va[4] = {va4.x, va4.y, va4.z, va4.w};
            float dv[4];
            #pragma unroll
            for (int q = 0; q < 4; q++) dv[q] = v3[q] * O1[q] + va[q];
            *(float4*)&out[(size_t)NN * HID + base] = make_float4(dv[0], dv[1], dv[2], dv[3]);
        }
    }
}

// ======================= launch =======================
extern "C" void kernel_launch(void* const* d_in, const int* in_sizes, int n_in,
                              void* d_out, int out_size) {
    const float* h     = (const float*)d_in[0];
    const float* vec   = (const float*)d_in[1];
    const float* coord = (const float*)d_in[2];
    const int*   ei    = (const int*)  d_in[3];
    const float* eattr = (const float*)d_in[4];
    const float* Wvp   = (const float*)d_in[5];
    const float* W1    = (const float*)d_in[6];
    const float* b1    = (const float*)d_in[7];
    const float* W2    = (const float*)d_in[8];
    const float* b2    = (const float*)d_in[9];
    const float* W3    = (const float*)d_in[10];
    const float* b3    = (const float*)d_in[11];
    const float* Wop   = (const float*)d_in[12];
    const float* bop   = (const float*)d_in[13];
    float* out = (float*)d_out;

    k_zero<<<25000, 256>>>();                          // 6.4M float4 of accumulators
    k_node_pre<<<NN / 8, 128>>>(vec, Wvp);             // 6250 CTAs
    k_edge<<<EE / 16, 128>>>(h, coord, ei, eattr,
                             W1, b1, W2, b2, W3, b3);  // 25000 CTAs
    k_node_out<<<NN / 16, 128>>>(Wop, bop, out);       // 3125 CTAs
}